// round 7
// baseline (speedup 1.0000x reference)
#include <cuda_runtime.h>
#include <cstdint>

#define C_IN  64
#define OC    64
#define KNPTS 9
#define PLANE 16384
#define KTOT  576

#define THREADS 256
#define PIXB   128                  // pixels per block (M)
#define NBLK   (4 * PLANE / PIXB)   // 512

// ---- scratch (__device__ globals: allocation is forbidden) ----
__device__ float    g_xhwc[(size_t)4 * PLANE * C_IN];   // NHWC x
__device__ uint32_t g_w0[KNPTS * OC * 32];              // bf16-hi pairs [kn][oc][kp]
__device__ uint32_t g_w1[KNPTS * OC * 32];              // bf16-lo pairs

// ---- dynamic smem layout (bytes) ----
#define SM_A0     0                 // A hi: 128 x 32 words (bf16x2), swizzled  (16384)
#define SM_A1     16384             // A lo                                     (16384)
#define SM_B0     32768             // B hi: 64 x 32 words                      (8192)
#define SM_B1     40960             // B lo                                     (8192)
#define SM_INTERP 49152             // 1152 x 12B                               (13824)
#define SM_TOTAL  62976
#define CS_STRIDE 132               // epilogue C stage row stride (floats)

// word-index swizzles: bank code = {ks^rhi bits | r0 | u} -> 32 distinct per warp
#define AIDX(p, kp)  (((p)  << 5) + ((kp) ^ (((p)  & 7) << 2)))
#define BIDX(oc, kp) (((oc) << 5) + ((kp) ^ (((oc) & 7) << 2)))

__device__ __forceinline__ uint32_t pack_bf16x2(float lo, float hi) {
    uint32_t r;   // d.hi = cvt(hi), d.lo = cvt(lo)
    asm("cvt.rn.bf16x2.f32 %0, %1, %2;" : "=r"(r) : "f"(hi), "f"(lo));
    return r;
}
__device__ __forceinline__ float unpack_lo(uint32_t w) { return __uint_as_float(w << 16); }
__device__ __forceinline__ float unpack_hi(uint32_t w) { return __uint_as_float(w & 0xFFFF0000u); }

#define MMA(C, A, B)                                                            \
    asm volatile("mma.sync.aligned.m16n8k16.row.col.f32.bf16.bf16.f32 "         \
                 "{%0,%1,%2,%3},{%4,%5,%6,%7},{%8,%9},{%0,%1,%2,%3};"           \
                 : "+f"(C[0]), "+f"(C[1]), "+f"(C[2]), "+f"(C[3])               \
                 : "r"(A[0]), "r"(A[1]), "r"(A[2]), "r"(A[3]), "r"(B[0]), "r"(B[1]))

// ---------------- NCHW -> NHWC transpose (float4 both sides) ----------------
__global__ __launch_bounds__(256)
void nchw_to_nhwc_kernel(const float* __restrict__ x)
{
    __shared__ float t[64][129];
    const int n   = blockIdx.x >> 7;
    const int hw0 = (blockIdx.x & 127) << 7;     // 128 pixels per tile
    const int tid = threadIdx.x;
    const float* xn = x + ((size_t)n << 20);
#pragma unroll
    for (int k = 0; k < 8; k++) {
        const int idx = tid + k * 256;           // 2048 float4 loads
        const int c = idx >> 5, q = idx & 31;
        const float4 v = *(const float4*)(xn + ((size_t)c << 14) + hw0 + 4 * q);
        t[c][4 * q] = v.x; t[c][4 * q + 1] = v.y; t[c][4 * q + 2] = v.z; t[c][4 * q + 3] = v.w;
    }
    __syncthreads();
    float* dst = g_xhwc + (((size_t)n << 14) + hw0) * 64;
#pragma unroll
    for (int k = 0; k < 8; k++) {
        const int idx = tid + k * 256;           // 2048 float4 stores
        const int p = idx >> 4, cq = idx & 15;
        float4 v;
        v.x = t[4 * cq][p]; v.y = t[4 * cq + 1][p]; v.z = t[4 * cq + 2][p]; v.w = t[4 * cq + 3][p];
        *(float4*)(dst + (size_t)p * 64 + 4 * cq) = v;
    }
}

// ------- weight: permute to [kn][oc][kp] + bf16 hi/lo split (packed pairs) -------
__global__ __launch_bounds__(256)
void wsplit_kernel(const float* __restrict__ w)
{
    const int i = blockIdx.x * 256 + threadIdx.x;   // i = kn*2048 + oc*32 + kp
    if (i < KNPTS * OC * 32) {
        const int kn = i >> 11, r = i & 2047;
        const int oc = r >> 5, kp = r & 31;
        const int c = 2 * kp;
        const float v0 = w[oc * KTOT + c * KNPTS + kn];
        const float v1 = w[oc * KTOT + (c + 1) * KNPTS + kn];
        const uint32_t h = pack_bf16x2(v0, v1);
        g_w0[i] = h;
        g_w1[i] = pack_bf16x2(v0 - unpack_lo(h), v1 - unpack_hi(h));
    }
}

// ---------------- main kernel: sample -> 3xBF16 mma.sync GEMM ----------------
struct Interp { short x0, y0; float fx, fy; };

extern __shared__ char smem[];

__global__ __launch_bounds__(THREADS, 3)
void dcn_mma_kernel(const float* __restrict__ offset, float* __restrict__ out)
{
    const int tid  = threadIdx.x;
    const int wid  = tid >> 5;
    const int lane = tid & 31;
    const int n       = blockIdx.x >> 7;            // 128 blocks per image
    const int pixbase = (blockIdx.x & 127) << 7;    // 128 consecutive pixels

    const float* offn = offset + (size_t)n * (KNPTS * 2) * PLANE;
    const float* xb   = g_xhwc + (((size_t)n) << 14) * 64;

    uint32_t* A0 = (uint32_t*)(smem + SM_A0);
    uint32_t* A1 = (uint32_t*)(smem + SM_A1);
    uint32_t* B0 = (uint32_t*)(smem + SM_B0);
    uint32_t* B1 = (uint32_t*)(smem + SM_B1);
    Interp* interp = (Interp*)(smem + SM_INTERP);

    // ---- Phase 1: interp metadata per (pixel, kernel-point) ----
    for (int it = tid; it < PIXB * KNPTS; it += THREADS) {
        const int p  = it / 9;
        const int kn = it - p * 9;
        const int pix = pixbase + p;
        const int oh = pix >> 7, ow = pix & 127;
        const float iy = (float)oh + offn[(2 * kn)     * PLANE + pix];
        const float ix = (float)ow + offn[(2 * kn + 1) * PLANE + pix];
        const float y0f = floorf(iy), x0f = floorf(ix);
        Interp t; t.x0 = (short)x0f; t.y0 = (short)y0f; t.fx = ix - x0f; t.fy = iy - y0f;
        interp[it] = t;
    }

    const int tg = tid >> 4;        // sampling task group 0..15
    const int lh = tid & 15;        // channel quad owner: channels 4lh..4lh+3

    // GEMM warp tiling: 4 warps along M, 2 along N; warp tile 32x32
    const int m0 = (wid & 3) * 32;
    const int n0 = (wid >> 2) * 32;
    const int r  = lane >> 2;       // fragment row group (0..7)
    const int u  = lane & 3;        // fragment k-pair slot (0..3)

    float acc[2][4][4];
#pragma unroll
    for (int mt = 0; mt < 2; mt++)
#pragma unroll
        for (int nt = 0; nt < 4; nt++)
#pragma unroll
            for (int q = 0; q < 4; q++) acc[mt][nt][q] = 0.f;

    for (int kn = 0; kn < KNPTS; kn++) {
        __syncthreads();   // prev GEMM reads done (and interp ready on kn==0)

        // ---- sample 128 pixels x 64 ch, bf16 hi/lo split, swizzled STS.64 ----
#pragma unroll
        for (int it = 0; it < 8; it++) {
            const int p = it * 16 + tg;
            const Interp t = interp[p * 9 + kn];
            const int x0 = t.x0, y0 = t.y0, x1 = x0 + 1, y1 = y0 + 1;
            const float wx1 = t.fx, wy1 = t.fy;
            const float wx0 = 1.f - wx1, wy0 = 1.f - wy1;
            const float mx0 = ((unsigned)x0 < 128u) ? 1.f : 0.f;
            const float mx1 = ((unsigned)x1 < 128u) ? 1.f : 0.f;
            const float my0 = ((unsigned)y0 < 128u) ? 1.f : 0.f;
            const float my1 = ((unsigned)y1 < 128u) ? 1.f : 0.f;
            const int cx0 = min(max((int)x0, 0), 127), cx1 = min(max((int)x1, 0), 127);
            const int cy0 = min(max((int)y0, 0), 127), cy1 = min(max((int)y1, 0), 127);
            const float w00 = wx0 * wy0 * mx0 * my0;
            const float w01 = wx1 * wy0 * mx1 * my0;
            const float w10 = wx0 * wy1 * mx0 * my1;
            const float w11 = wx1 * wy1 * mx1 * my1;
            const float4 a = *(const float4*)(xb + (((cy0 << 7) + cx0) << 6) + 4 * lh);
            const float4 b = *(const float4*)(xb + (((cy0 << 7) + cx1) << 6) + 4 * lh);
            const float4 c = *(const float4*)(xb + (((cy1 << 7) + cx0) << 6) + 4 * lh);
            const float4 d = *(const float4*)(xb + (((cy1 << 7) + cx1) << 6) + 4 * lh);
            float v0 = w00 * a.x + w01 * b.x + w10 * c.x + w11 * d.x;
            float v1 = w00 * a.y + w01 * b.y + w10 * c.y + w11 * d.y;
            float v2 = w00 * a.z + w01 * b.z + w10 * c.z + w11 * d.z;
            float v3 = w00 * a.w + w01 * b.w + w10 * c.w + w11 * d.w;
            uint2 hi, lo;
            hi.x = pack_bf16x2(v0, v1);
            hi.y = pack_bf16x2(v2, v3);
            lo.x = pack_bf16x2(v0 - unpack_lo(hi.x), v1 - unpack_hi(hi.x));
            lo.y = pack_bf16x2(v2 - unpack_lo(hi.y), v3 - unpack_hi(hi.y));
            const int wix = AIDX(p, 2 * lh);    // even -> 8B aligned, pair stays adjacent
            *(uint2*)&A0[wix] = hi;
            *(uint2*)&A1[wix] = lo;
        }

        // ---- stage weight chunk (packed bf16 pairs) into swizzled B tiles ----
#pragma unroll
        for (int k = 0; k < 4; k++) {
            const int i = tid + k * 256;        // 1024 uint2 units
            const int oc = i >> 4, q = i & 15;
            const int wix = BIDX(oc, 2 * q);
            const int gi  = (kn << 11) + (oc << 5) + 2 * q;
            *(uint2*)&B0[wix] = *(const uint2*)&g_w0[gi];
            *(uint2*)&B1[wix] = *(const uint2*)&g_w1[gi];
        }
        __syncthreads();

        // ---- GEMM: 4 k16-steps, 3xBF16 compensation ----
#pragma unroll
        for (int ks = 0; ks < 4; ks++) {
            const int kp0 = ks * 8 + u, kp1 = kp0 + 4;
            uint32_t a0[2][4], a1[2][4];
#pragma unroll
            for (int mt = 0; mt < 2; mt++) {
                const int p0 = m0 + mt * 16 + r, p1 = p0 + 8;
                const int i00 = AIDX(p0, kp0), i10 = AIDX(p1, kp0);
                const int i01 = AIDX(p0, kp1), i11 = AIDX(p1, kp1);
                a0[mt][0] = A0[i00]; a0[mt][1] = A0[i10]; a0[mt][2] = A0[i01]; a0[mt][3] = A0[i11];
                a1[mt][0] = A1[i00]; a1[mt][1] = A1[i10]; a1[mt][2] = A1[i01]; a1[mt][3] = A1[i11];
            }
            uint32_t b0[4][2], b1[4][2];
#pragma unroll
            for (int nt = 0; nt < 4; nt++) {
                const int oc = n0 + nt * 8 + r;
                const int j0 = BIDX(oc, kp0), j1 = BIDX(oc, kp1);
                b0[nt][0] = B0[j0]; b0[nt][1] = B0[j1];
                b1[nt][0] = B1[j0]; b1[nt][1] = B1[j1];
            }
#pragma unroll
            for (int mt = 0; mt < 2; mt++)
#pragma unroll
                for (int nt = 0; nt < 4; nt++) {
                    MMA(acc[mt][nt], a1[mt], b0[nt]);   // lo-x * hi-w
                    MMA(acc[mt][nt], a0[mt], b1[nt]);   // hi-x * lo-w
                    MMA(acc[mt][nt], a0[mt], b0[nt]);   // hi-x * hi-w
                }
        }
    }

    // ---- epilogue: stage C in smem (oc-major), then coalesced STG.128 ----
    __syncthreads();
    float* Cs = (float*)smem;   // 64 x CS_STRIDE floats (33792B, tiles dead)
#pragma unroll
    for (int mt = 0; mt < 2; mt++)
#pragma unroll
        for (int nt = 0; nt < 4; nt++) {
            const int p  = m0 + mt * 16 + r;
            const int oc = n0 + nt * 8 + 2 * u;
            Cs[oc * CS_STRIDE + p]           = acc[mt][nt][0];
            Cs[(oc + 1) * CS_STRIDE + p]     = acc[mt][nt][1];
            Cs[oc * CS_STRIDE + p + 8]       = acc[mt][nt][2];
            Cs[(oc + 1) * CS_STRIDE + p + 8] = acc[mt][nt][3];
        }
    __syncthreads();
    float* ob = out + (((size_t)n * OC) << 14) + pixbase;
#pragma unroll
    for (int k = 0; k < 8; k++) {
        const int idx = tid + k * 256;          // float4 id
        const int oc = idx >> 5, fq = idx & 31;
        const float4 v = *(const float4*)(Cs + oc * CS_STRIDE + fq * 4);
        *(float4*)(ob + ((size_t)oc << 14) + fq * 4) = v;
    }
}

extern "C" void kernel_launch(void* const* d_in, const int* in_sizes, int n_in,
                              void* d_out, int out_size)
{
    const float* x      = (const float*)d_in[0];   // (4, 64, 128, 128)
    const float* offset = (const float*)d_in[1];   // (4, 18, 128, 128)
    const float* weight = (const float*)d_in[2];   // (64, 64, 9)
    float* out = (float*)d_out;                    // (4, 64, 128, 128)
    (void)in_sizes; (void)n_in; (void)out_size;

    static int smem_set = 0;
    if (!smem_set) {
        cudaFuncSetAttribute(dcn_mma_kernel,
                             cudaFuncAttributeMaxDynamicSharedMemorySize, SM_TOTAL);
        smem_set = 1;
    }
    nchw_to_nhwc_kernel<<<4 * 128, 256>>>(x);
    wsplit_kernel<<<(KNPTS * OC * 32 + 255) / 256, 256>>>(weight);
    dcn_mma_kernel<<<NBLK, THREADS, SM_TOTAL>>>(offset, out);
}

// round 8
// speedup vs baseline: 1.6007x; 1.6007x over previous
#include <cuda_runtime.h>
#include <cstdint>

#define C_IN  64
#define OC    64
#define KNPTS 9
#define PLANE 16384
#define KTOT  576

#define THREADS 256
#define PIXB   128                  // pixels per block (M)
#define NBLK   (4 * PLANE / PIXB)   // 512

// ---- scratch (__device__ globals: allocation is forbidden) ----
__device__ float    g_xhwc[(size_t)4 * PLANE * C_IN];   // NHWC x
__device__ uint32_t g_w0[KNPTS * OC * 32];              // bf16-hi pairs [kn][oc][kp]
__device__ uint32_t g_w1[KNPTS * OC * 32];              // bf16-lo pairs

// ---- dynamic smem layout (bytes) ----
#define SM_A0     0                 // A hi: 128 x 32 words (bf16x2), swizzled  (16384)
#define SM_A1     16384             // A lo                                     (16384)
#define SM_B0     32768             // B hi: 64 x 32 words                      (8192)
#define SM_B1     40960             // B lo                                     (8192)
#define SM_INTERP 49152             // 1152 x 12B                               (13824)
#define SM_TOTAL  62976
#define CS_STRIDE 132               // epilogue C stage row stride (floats)

// word-index swizzles (swizzle bits 2-4 only; 16B groups stay contiguous)
#define AIDX(p, kp)  (((p)  << 5) + ((kp) ^ (((p)  & 7) << 2)))
#define BIDX(oc, kp) (((oc) << 5) + ((kp) ^ (((oc) & 7) << 2)))

__device__ __forceinline__ uint32_t pack_bf16x2(float lo, float hi) {
    uint32_t r;   // d.hi = cvt(hi), d.lo = cvt(lo)
    asm("cvt.rn.bf16x2.f32 %0, %1, %2;" : "=r"(r) : "f"(hi), "f"(lo));
    return r;
}
__device__ __forceinline__ float unpack_lo(uint32_t w) { return __uint_as_float(w << 16); }
__device__ __forceinline__ float unpack_hi(uint32_t w) { return __uint_as_float(w & 0xFFFF0000u); }

__device__ __forceinline__ uint32_t smem_u32(const void* p) {
    uint32_t a;
    asm("{ .reg .u64 t; cvta.to.shared.u64 t, %1; cvt.u32.u64 %0, t; }" : "=r"(a) : "l"(p));
    return a;
}
__device__ __forceinline__ void ldm4(uint32_t* d, uint32_t addr) {
    asm volatile("ldmatrix.sync.aligned.m8n8.x4.shared.b16 {%0,%1,%2,%3}, [%4];"
                 : "=r"(d[0]), "=r"(d[1]), "=r"(d[2]), "=r"(d[3]) : "r"(addr));
}
__device__ __forceinline__ void ldm2(uint32_t* d, uint32_t addr) {
    asm volatile("ldmatrix.sync.aligned.m8n8.x2.shared.b16 {%0,%1}, [%2];"
                 : "=r"(d[0]), "=r"(d[1]) : "r"(addr));
}

#define MMA(C, A, B)                                                            \
    asm volatile("mma.sync.aligned.m16n8k16.row.col.f32.bf16.bf16.f32 "         \
                 "{%0,%1,%2,%3},{%4,%5,%6,%7},{%8,%9},{%0,%1,%2,%3};"           \
                 : "+f"(C[0]), "+f"(C[1]), "+f"(C[2]), "+f"(C[3])               \
                 : "r"(A[0]), "r"(A[1]), "r"(A[2]), "r"(A[3]), "r"(B[0]), "r"(B[1]))

// ---------------- NCHW -> NHWC transpose (float4 both sides) ----------------
__global__ __launch_bounds__(256)
void nchw_to_nhwc_kernel(const float* __restrict__ x)
{
    __shared__ float t[64][129];
    const int n   = blockIdx.x >> 7;
    const int hw0 = (blockIdx.x & 127) << 7;     // 128 pixels per tile
    const int tid = threadIdx.x;
    const float* xn = x + ((size_t)n << 20);
#pragma unroll
    for (int k = 0; k < 8; k++) {
        const int idx = tid + k * 256;
        const int c = idx >> 5, q = idx & 31;
        const float4 v = *(const float4*)(xn + ((size_t)c << 14) + hw0 + 4 * q);
        t[c][4 * q] = v.x; t[c][4 * q + 1] = v.y; t[c][4 * q + 2] = v.z; t[c][4 * q + 3] = v.w;
    }
    __syncthreads();
    float* dst = g_xhwc + (((size_t)n << 14) + hw0) * 64;
#pragma unroll
    for (int k = 0; k < 8; k++) {
        const int idx = tid + k * 256;
        const int p = idx >> 4, cq = idx & 15;
        float4 v;
        v.x = t[4 * cq][p]; v.y = t[4 * cq + 1][p]; v.z = t[4 * cq + 2][p]; v.w = t[4 * cq + 3][p];
        *(float4*)(dst + (size_t)p * 64 + 4 * cq) = v;
    }
}

// ------- weight: permute to [kn][oc][kp] + bf16 hi/lo split (packed pairs) -------
__global__ __launch_bounds__(256)
void wsplit_kernel(const float* __restrict__ w)
{
    const int i = blockIdx.x * 256 + threadIdx.x;   // i = kn*2048 + oc*32 + kp
    if (i < KNPTS * OC * 32) {
        const int kn = i >> 11, r = i & 2047;
        const int oc = r >> 5, kp = r & 31;
        const int c = 2 * kp;
        const float v0 = w[oc * KTOT + c * KNPTS + kn];
        const float v1 = w[oc * KTOT + (c + 1) * KNPTS + kn];
        const uint32_t h = pack_bf16x2(v0, v1);
        g_w0[i] = h;
        g_w1[i] = pack_bf16x2(v0 - unpack_lo(h), v1 - unpack_hi(h));
    }
}

// ---------------- main kernel: sample -> 3xBF16 mma.sync GEMM ----------------
struct Interp { short x0, y0; float fx, fy; };

extern __shared__ char smem[];

__global__ __launch_bounds__(THREADS, 2)
void dcn_mma_kernel(const float* __restrict__ offset, float* __restrict__ out)
{
    const int tid  = threadIdx.x;
    const int wid  = tid >> 5;
    const int lane = tid & 31;
    const int n       = blockIdx.x >> 7;            // 128 blocks per image
    const int pixbase = (blockIdx.x & 127) << 7;    // 128 consecutive pixels

    const float* offn = offset + (size_t)n * (KNPTS * 2) * PLANE;
    const float* xb   = g_xhwc + (((size_t)n) << 14) * 64;

    uint32_t* A0 = (uint32_t*)(smem + SM_A0);
    uint32_t* A1 = (uint32_t*)(smem + SM_A1);
    uint32_t* B0 = (uint32_t*)(smem + SM_B0);
    uint32_t* B1 = (uint32_t*)(smem + SM_B1);
    Interp* interp = (Interp*)(smem + SM_INTERP);
    const uint32_t a0b = smem_u32(A0), a1b = smem_u32(A1);
    const uint32_t b0b = smem_u32(B0), b1b = smem_u32(B1);

    // ---- Phase 1: interp metadata per (pixel, kernel-point) ----
    for (int it = tid; it < PIXB * KNPTS; it += THREADS) {
        const int p  = it / 9;
        const int kn = it - p * 9;
        const int pix = pixbase + p;
        const int oh = pix >> 7, ow = pix & 127;
        const float iy = (float)oh + offn[(2 * kn)     * PLANE + pix];
        const float ix = (float)ow + offn[(2 * kn + 1) * PLANE + pix];
        const float y0f = floorf(iy), x0f = floorf(ix);
        Interp t; t.x0 = (short)x0f; t.y0 = (short)y0f; t.fx = ix - x0f; t.fy = iy - y0f;
        interp[it] = t;
    }

    const int tg = tid >> 4;        // sampling task group 0..15
    const int lh = tid & 15;        // channel quad owner: channels 4lh..4lh+3

    // GEMM warp tiling: 4 warps along M, 2 along N; warp tile 32x32
    const int m0 = (wid & 3) * 32;
    const int n0 = (wid >> 2) * 32;
    const int r  = lane >> 2;       // fragment row group (0..7)
    const int u  = lane & 3;        // fragment k-pair slot (0..3)

    // ldmatrix per-lane base addresses (word units; kg XOR folded in per-ks)
    const int l7   = lane & 7;
    const int swz  = l7 << 2;                       // row&7 is lane&7 for A and B rows
    const int arow0 = m0 + l7 + (((lane >> 3) & 1) << 3);   // + mt*16
    const int kbA   = ((lane >> 4) & 1) << 2;
    const int browl = n0 + l7;                      // + nt*8 (lanes 0..15 meaningful)
    const int kbB   = ((lane >> 3) & 1) << 2;

    float acc[2][4][4];
#pragma unroll
    for (int mt = 0; mt < 2; mt++)
#pragma unroll
        for (int nt = 0; nt < 4; nt++)
#pragma unroll
            for (int q = 0; q < 4; q++) acc[mt][nt][q] = 0.f;

    for (int kn = 0; kn < KNPTS; kn++) {
        __syncthreads();   // prev GEMM reads done (and interp ready on kn==0)

        // ---- sample 128 pixels x 64 ch, bf16 hi/lo split, swizzled STS.64 ----
#pragma unroll
        for (int it = 0; it < 8; it++) {
            const int p = it * 16 + tg;
            const Interp t = interp[p * 9 + kn];
            const int x0 = t.x0, y0 = t.y0, x1 = x0 + 1, y1 = y0 + 1;
            const float wx1 = t.fx, wy1 = t.fy;
            const float wx0 = 1.f - wx1, wy0 = 1.f - wy1;
            const float mx0 = ((unsigned)x0 < 128u) ? 1.f : 0.f;
            const float mx1 = ((unsigned)x1 < 128u) ? 1.f : 0.f;
            const float my0 = ((unsigned)y0 < 128u) ? 1.f : 0.f;
            const float my1 = ((unsigned)y1 < 128u) ? 1.f : 0.f;
            const int cx0 = min(max((int)x0, 0), 127), cx1 = min(max((int)x1, 0), 127);
            const int cy0 = min(max((int)y0, 0), 127), cy1 = min(max((int)y1, 0), 127);
            const float w00 = wx0 * wy0 * mx0 * my0;
            const float w01 = wx1 * wy0 * mx1 * my0;
            const float w10 = wx0 * wy1 * mx0 * my1;
            const float w11 = wx1 * wy1 * mx1 * my1;
            const float4 a = *(const float4*)(xb + (((cy0 << 7) + cx0) << 6) + 4 * lh);
            const float4 b = *(const float4*)(xb + (((cy0 << 7) + cx1) << 6) + 4 * lh);
            const float4 c = *(const float4*)(xb + (((cy1 << 7) + cx0) << 6) + 4 * lh);
            const float4 d = *(const float4*)(xb + (((cy1 << 7) + cx1) << 6) + 4 * lh);
            float v0 = w00 * a.x + w01 * b.x + w10 * c.x + w11 * d.x;
            float v1 = w00 * a.y + w01 * b.y + w10 * c.y + w11 * d.y;
            float v2 = w00 * a.z + w01 * b.z + w10 * c.z + w11 * d.z;
            float v3 = w00 * a.w + w01 * b.w + w10 * c.w + w11 * d.w;
            uint2 hi, lo;
            hi.x = pack_bf16x2(v0, v1);
            hi.y = pack_bf16x2(v2, v3);
            lo.x = pack_bf16x2(v0 - unpack_lo(hi.x), v1 - unpack_hi(hi.x));
            lo.y = pack_bf16x2(v2 - unpack_lo(hi.y), v3 - unpack_hi(hi.y));
            const int wix = AIDX(p, 2 * lh);
            *(uint2*)&A0[wix] = hi;
            *(uint2*)&A1[wix] = lo;
        }

        // ---- stage weight chunk (packed bf16 pairs) into swizzled B tiles ----
#pragma unroll
        for (int k = 0; k < 4; k++) {
            const int i = tid + k * 256;
            const int oc = i >> 4, q = i & 15;
            const int wix = BIDX(oc, 2 * q);
            const int gi  = (kn << 11) + (oc << 5) + 2 * q;
            *(uint2*)&B0[wix] = *(const uint2*)&g_w0[gi];
            *(uint2*)&B1[wix] = *(const uint2*)&g_w1[gi];
        }
        __syncthreads();

        // ---- GEMM: 4 k16-steps, 3xBF16 compensation, ldmatrix fragments ----
#pragma unroll
        for (int ks = 0; ks < 4; ks++) {
            uint32_t a0[2][4], a1[2][4];
#pragma unroll
            for (int mt = 0; mt < 2; mt++) {
                const int row = arow0 + mt * 16;
                const uint32_t off =
                    (uint32_t)(((row << 5) + ((ks * 8 + kbA) ^ swz)) << 2);
                ldm4(a0[mt], a0b + off);
                ldm4(a1[mt], a1b + off);
            }
            uint32_t b0[4][2], b1[4][2];
#pragma unroll
            for (int nt = 0; nt < 4; nt++) {
                const int row = browl + nt * 8;
                const uint32_t off =
                    (uint32_t)(((row << 5) + ((ks * 8 + kbB) ^ swz)) << 2);
                ldm2(b0[nt], b0b + off);
                ldm2(b1[nt], b1b + off);
            }
#pragma unroll
            for (int mt = 0; mt < 2; mt++)
#pragma unroll
                for (int nt = 0; nt < 4; nt++) {
                    MMA(acc[mt][nt], a1[mt], b0[nt]);   // lo-x * hi-w
                    MMA(acc[mt][nt], a0[mt], b1[nt]);   // hi-x * lo-w
                    MMA(acc[mt][nt], a0[mt], b0[nt]);   // hi-x * hi-w
                }
        }
    }

    // ---- epilogue: stage C in smem (oc-major), then coalesced STG.128 ----
    __syncthreads();
    float* Cs = (float*)smem;   // 64 x CS_STRIDE floats (tiles dead)
#pragma unroll
    for (int mt = 0; mt < 2; mt++)
#pragma unroll
        for (int nt = 0; nt < 4; nt++) {
            const int p  = m0 + mt * 16 + r;
            const int oc = n0 + nt * 8 + 2 * u;
            Cs[oc * CS_STRIDE + p]           = acc[mt][nt][0];
            Cs[(oc + 1) * CS_STRIDE + p]     = acc[mt][nt][1];
            Cs[oc * CS_STRIDE + p + 8]       = acc[mt][nt][2];
            Cs[(oc + 1) * CS_STRIDE + p + 8] = acc[mt][nt][3];
        }
    __syncthreads();
    float* ob = out + (((size_t)n * OC) << 14) + pixbase;
#pragma unroll
    for (int k = 0; k < 8; k++) {
        const int idx = tid + k * 256;
        const int oc = idx >> 5, fq = idx & 31;
        const float4 v = *(const float4*)(Cs + oc * CS_STRIDE + fq * 4);
        *(float4*)(ob + ((size_t)oc << 14) + fq * 4) = v;
    }
}

extern "C" void kernel_launch(void* const* d_in, const int* in_sizes, int n_in,
                              void* d_out, int out_size)
{
    const float* x      = (const float*)d_in[0];   // (4, 64, 128, 128)
    const float* offset = (const float*)d_in[1];   // (4, 18, 128, 128)
    const float* weight = (const float*)d_in[2];   // (64, 64, 9)
    float* out = (float*)d_out;                    // (4, 64, 128, 128)
    (void)in_sizes; (void)n_in; (void)out_size;

    static int smem_set = 0;
    if (!smem_set) {
        cudaFuncSetAttribute(dcn_mma_kernel,
                             cudaFuncAttributeMaxDynamicSharedMemorySize, SM_TOTAL);
        smem_set = 1;
    }
    nchw_to_nhwc_kernel<<<4 * 128, 256>>>(x);
    wsplit_kernel<<<(KNPTS * OC * 32 + 255) / 256, 256>>>(weight);
    dcn_mma_kernel<<<NBLK, THREADS, SM_TOTAL>>>(offset, out);
}